// round 4
// baseline (speedup 1.0000x reference)
#include <cuda_runtime.h>
#include <cstdint>

#define T_TOK   8192
#define HID     1024
#define FFN_DIM 4096
#define NEXP    8
#define TOTAL   (2 * T_TOK)
#define TOTPAD  (TOTAL + 128)

#define BM 128
#define BN 128
#define BK 32
#define AST 36          /* A smem row stride (floats) */
#define BST 136         /* B smem row stride (floats) */
#define ABYTES (BM * AST * 4)
#define BBYTES (BK * BST * 4)
#define SMEM_TOTAL (2 * (ABYTES + BBYTES))

__device__ int   g_counts[NEXP];
__device__ int   g_offsets[NEXP];
__device__ int   g_writePos[NEXP];
__device__ int   g_top2[T_TOK * 2];
__device__ int   g_entries[TOTAL];
__device__ float g_xg[(size_t)TOTPAD * HID];
__device__ float g_w1r[(size_t)NEXP * HID * FFN_DIM];
__device__ float g_w2r[(size_t)NEXP * FFN_DIM * HID];
__device__ float g_h1[(size_t)TOTPAD * FFN_DIM];
__device__ float g_partial[(size_t)2 * T_TOK * HID];

__device__ __forceinline__ float rna_tf32(float f) {
    uint32_t u;
    asm("cvt.rna.tf32.f32 %0, %1;" : "=r"(u) : "f"(f));
    return __uint_as_float(u);
}
__device__ __forceinline__ uint32_t smem_u32(const void* p) {
    uint32_t a;
    asm("{ .reg .u64 t; cvta.to.shared.u64 t, %1; cvt.u32.u64 %0, t; }" : "=r"(a) : "l"(p));
    return a;
}
#define CPA16(dst, src) asm volatile("cp.async.cg.shared.global [%0], [%1], 16;" :: "r"(dst), "l"(src) : "memory")

__device__ __forceinline__ void mma_tf32(float* c, const uint32_t* a, const uint32_t* b) {
    asm volatile("mma.sync.aligned.m16n8k8.row.col.f32.tf32.tf32.f32 "
                 "{%0,%1,%2,%3}, {%4,%5,%6,%7}, {%8,%9}, {%0,%1,%2,%3};"
                 : "+f"(c[0]), "+f"(c[1]), "+f"(c[2]), "+f"(c[3])
                 : "r"(a[0]), "r"(a[1]), "r"(a[2]), "r"(a[3]), "r"(b[0]), "r"(b[1]));
}

// ---------------- routing ----------------
__global__ void zero_counts_kernel() {
    if (threadIdx.x < NEXP) g_counts[threadIdx.x] = 0;
}

__global__ void gate_kernel(const float* __restrict__ x,
                            const float* __restrict__ gate_w,
                            const float* __restrict__ gate_b) {
    int warp = (blockIdx.x * blockDim.x + threadIdx.x) >> 5;
    int lane = threadIdx.x & 31;
    if (warp >= T_TOK) return;
    const float* xr = x + (size_t)warp * HID;
    float acc[NEXP];
#pragma unroll
    for (int e = 0; e < NEXP; e++) acc[e] = 0.f;
    for (int h = lane; h < HID; h += 32) {
        float xv = xr[h];
#pragma unroll
        for (int e = 0; e < NEXP; e++) acc[e] += xv * gate_w[h * NEXP + e];
    }
#pragma unroll
    for (int e = 0; e < NEXP; e++)
#pragma unroll
        for (int o = 16; o > 0; o >>= 1)
            acc[e] += __shfl_down_sync(0xffffffffu, acc[e], o);
    if (lane == 0) {
        float v1 = -3.4e38f, v2 = -3.4e38f;
        int i1 = 0, i2 = 0;
#pragma unroll
        for (int e = 0; e < NEXP; e++) {
            float v = acc[e] + gate_b[e];
            if (v > v1) { v2 = v1; i2 = i1; v1 = v; i1 = e; }
            else if (v > v2) { v2 = v; i2 = e; }
        }
        g_top2[warp * 2 + 0] = i1;
        g_top2[warp * 2 + 1] = i2;
        atomicAdd(&g_counts[i1], 1);
        atomicAdd(&g_counts[i2], 1);
    }
}

__global__ void scan_kernel() {
    if (threadIdx.x == 0) {
        int off = 0;
        for (int e = 0; e < NEXP; e++) {
            g_offsets[e] = off; g_writePos[e] = off; off += g_counts[e];
        }
    }
}

__global__ void fill_kernel() {
    int t = blockIdx.x * blockDim.x + threadIdx.x;
    if (t >= T_TOK) return;
    int p0 = atomicAdd(&g_writePos[g_top2[t * 2 + 0]], 1);
    g_entries[p0] = t * 2;
    int p1 = atomicAdd(&g_writePos[g_top2[t * 2 + 1]], 1);
    g_entries[p1] = t * 2 + 1;
}

__global__ void gather_kernel(const float* __restrict__ x) {
    int tok = g_entries[blockIdx.x] >> 1;
    float4 v = ((const float4*)(x + (size_t)tok * HID))[threadIdx.x];
    v.x = rna_tf32(v.x); v.y = rna_tf32(v.y); v.z = rna_tf32(v.z); v.w = rna_tf32(v.w);
    ((float4*)(g_xg + (size_t)blockIdx.x * HID))[threadIdx.x] = v;
}

__global__ void round_copy_kernel(const float4* __restrict__ src,
                                  float4* __restrict__ dst, size_t n4) {
    size_t stride = (size_t)gridDim.x * blockDim.x;
    for (size_t i = blockIdx.x * (size_t)blockDim.x + threadIdx.x; i < n4; i += stride) {
        float4 v = src[i];
        v.x = rna_tf32(v.x); v.y = rna_tf32(v.y);
        v.z = rna_tf32(v.z); v.w = rna_tf32(v.w);
        dst[i] = v;
    }
}

// ---------------- tf32 mma.sync grouped GEMM ----------------
// MODE1: A=g_xg (K=HID), B=g_w1r [H][F], out=rna(relu(.+b1)) -> g_h1
// MODE2: A=g_h1 (K=FFN), B=g_w2r [F][H], out=.+b2 scattered -> g_partial
template<int KDIM, int NPITCH, bool MODE1>
__global__ __launch_bounds__(256, 2)
void gemm_mma_kernel(const float* __restrict__ Bw, const float* __restrict__ bias) {
    const int e = blockIdx.z, mt = blockIdx.y, nt = blockIdx.x;
    const int count = g_counts[e];
    if (mt * BM >= count) return;
    const int base = g_offsets[e];

    extern __shared__ __align__(16) uint8_t smem[];
    float* Asm = (float*)smem;                    // [2][BM][AST]
    float* Bsm = (float*)(smem + 2 * ABYTES);     // [2][BK][BST]
    const uint32_t sA0 = smem_u32(Asm);
    const uint32_t sB0 = smem_u32(Bsm);

    const int tid = threadIdx.x;
    const int lane = tid & 31, wid = tid >> 5;
    const int wm = (wid >> 2) * 64;               // 0 / 64
    const int wn = (wid & 3) * 32;                // 0..96
    const int grp = lane >> 2, tg = lane & 3;

    // loader geometry: A 1 row/thread (r=tid>>1), B 1 row/8 threads
    const int arow = tid >> 1, acol = (tid & 1) * 16;
    const int brow = tid >> 3, bcol = (tid & 7) * 16;
    const float* Ag = MODE1 ? g_xg : g_h1;
    const float* aSrc = Ag + (size_t)(base + mt * BM + arow) * KDIM + acol;
    const float* bSrc = Bw + (size_t)e * HID * FFN_DIM
                           + (size_t)brow * NPITCH + nt * BN + bcol;
    const uint32_t aDst = sA0 + (uint32_t)(arow * AST + acol) * 4;
    const uint32_t bDst = sB0 + (uint32_t)(brow * BST + bcol) * 4;

    float c[4][4][4];
#pragma unroll
    for (int im = 0; im < 4; im++)
#pragma unroll
        for (int jn = 0; jn < 4; jn++)
#pragma unroll
            for (int q = 0; q < 4; q++) c[im][jn][q] = 0.f;

    constexpr int KT = KDIM / BK;

    // prologue: stage 0
#pragma unroll
    for (int i = 0; i < 4; i++) CPA16(aDst + i * 16, aSrc + i * 4);
#pragma unroll
    for (int i = 0; i < 4; i++) CPA16(bDst + i * 16, bSrc + i * 4);
    asm volatile("cp.async.commit_group;" ::: "memory");

    for (int kt = 0; kt < KT; kt++) {
        const int s = kt & 1;
        if (kt + 1 < KT) {
            const int s2 = (kt + 1) & 1;
            const float* a2 = aSrc + (kt + 1) * BK;
            const float* b2 = bSrc + (size_t)(kt + 1) * BK * NPITCH;
            const uint32_t ad2 = aDst + s2 * ABYTES;
            const uint32_t bd2 = bDst + s2 * BBYTES;
#pragma unroll
            for (int i = 0; i < 4; i++) CPA16(ad2 + i * 16, a2 + i * 4);
#pragma unroll
            for (int i = 0; i < 4; i++) CPA16(bd2 + i * 16, b2 + i * 4);
            asm volatile("cp.async.commit_group;" ::: "memory");
            asm volatile("cp.async.wait_group 1;" ::: "memory");
        } else {
            asm volatile("cp.async.wait_group 0;" ::: "memory");
        }
        __syncthreads();

        const float* As = Asm + s * (BM * AST);
        const float* Bs = Bsm + s * (BK * BST);
#pragma unroll
        for (int k8 = 0; k8 < 4; k8++) {
            const int kb = k8 * 8;
            uint32_t a[4][4], b[4][2];
#pragma unroll
            for (int im = 0; im < 4; im++) {
                const int r0 = wm + im * 16 + grp;
                a[im][0] = __float_as_uint(As[r0 * AST + kb + tg]);
                a[im][1] = __float_as_uint(As[(r0 + 8) * AST + kb + tg]);
                a[im][2] = __float_as_uint(As[r0 * AST + kb + tg + 4]);
                a[im][3] = __float_as_uint(As[(r0 + 8) * AST + kb + tg + 4]);
            }
#pragma unroll
            for (int jn = 0; jn < 4; jn++) {
                const int cn = wn + jn * 8 + grp;
                b[jn][0] = __float_as_uint(Bs[(kb + tg) * BST + cn]);
                b[jn][1] = __float_as_uint(Bs[(kb + tg + 4) * BST + cn]);
            }
#pragma unroll
            for (int im = 0; im < 4; im++)
#pragma unroll
                for (int jn = 0; jn < 4; jn++)
                    mma_tf32(c[im][jn], a[im], b[jn]);
        }
        __syncthreads();
    }

    // epilogue
    const float* bp = bias + (size_t)e * (MODE1 ? FFN_DIM : HID) + nt * BN;
#pragma unroll
    for (int im = 0; im < 4; im++) {
#pragma unroll
        for (int half = 0; half < 2; half++) {
            const int row = wm + im * 16 + grp + half * 8;
            const int grow = mt * BM + row;
            if (grow < count) {
                const int gi = base + grow;
                float* dst;
                if (MODE1) {
                    dst = g_h1 + (size_t)gi * FFN_DIM + nt * BN;
                } else {
                    const int en = g_entries[gi];
                    dst = g_partial + ((size_t)(en & 1) * T_TOK + (en >> 1)) * HID + nt * BN;
                }
#pragma unroll
                for (int jn = 0; jn < 4; jn++) {
                    const int col = wn + jn * 8 + tg * 2;
                    float v0 = c[im][jn][half * 2 + 0] + bp[col];
                    float v1 = c[im][jn][half * 2 + 1] + bp[col + 1];
                    if (MODE1) {
                        v0 = rna_tf32(fmaxf(v0, 0.f));
                        v1 = rna_tf32(fmaxf(v1, 0.f));
                    }
                    float2 o; o.x = v0; o.y = v1;
                    *(float2*)(dst + col) = o;
                }
            }
        }
    }
}

__global__ void combine_kernel(float* __restrict__ out) {
    int i = blockIdx.x * blockDim.x + threadIdx.x;
    if (i < T_TOK * HID / 4) {
        const float4* p0 = (const float4*)g_partial;
        const float4* p1 = (const float4*)(g_partial + (size_t)T_TOK * HID);
        float4 a = p0[i], b = p1[i], r;
        r.x = a.x + b.x; r.y = a.y + b.y; r.z = a.z + b.z; r.w = a.w + b.w;
        ((float4*)out)[i] = r;
    }
}

extern "C" void kernel_launch(void* const* d_in, const int* in_sizes, int n_in,
                              void* d_out, int out_size) {
    const float* x      = (const float*)d_in[0];
    const float* gate_w = (const float*)d_in[1];
    const float* gate_b = (const float*)d_in[2];
    const float* w1     = (const float*)d_in[3];
    const float* b1     = (const float*)d_in[4];
    const float* w2     = (const float*)d_in[5];
    const float* b2     = (const float*)d_in[6];
    float* out = (float*)d_out;

    cudaFuncSetAttribute(gemm_mma_kernel<HID, FFN_DIM, true>,
                         cudaFuncAttributeMaxDynamicSharedMemorySize, SMEM_TOTAL);
    cudaFuncSetAttribute(gemm_mma_kernel<FFN_DIM, HID, false>,
                         cudaFuncAttributeMaxDynamicSharedMemorySize, SMEM_TOTAL);

    zero_counts_kernel<<<1, 32>>>();
    gate_kernel<<<T_TOK / 8, 256>>>(x, gate_w, gate_b);
    scan_kernel<<<1, 32>>>();
    fill_kernel<<<T_TOK / 256, 256>>>();
    gather_kernel<<<TOTAL, HID / 4>>>(x);

    const size_t wn4 = (size_t)NEXP * HID * FFN_DIM / 4;
    round_copy_kernel<<<4096, 256>>>((const float4*)w1, (float4*)g_w1r, wn4);
    round_copy_kernel<<<4096, 256>>>((const float4*)w2, (float4*)g_w2r, wn4);

    gemm_mma_kernel<HID, FFN_DIM, true>
        <<<dim3(FFN_DIM / BN, 128, NEXP), 256, SMEM_TOTAL>>>(g_w1r, b1);
    gemm_mma_kernel<FFN_DIM, HID, false>
        <<<dim3(HID / BN, 128, NEXP), 256, SMEM_TOTAL>>>(g_w2r, b2);

    combine_kernel<<<T_TOK * HID / 4 / 256, 256>>>(out);
}

// round 5
// speedup vs baseline: 11.9082x; 11.9082x over previous
#include <cuda_runtime.h>
#include <cstdint>

#define T_TOK   8192
#define HID     1024
#define FFN_DIM 4096
#define NEXP    8
#define TOTAL   (2 * T_TOK)

#define BM 128
#define BN 128
#define BK 16
#define NTHREADS 256

typedef unsigned long long u64t;

// ---------------- scratch ----------------
__device__ int   g_counts[NEXP];
__device__ int   g_offsets[NEXP];
__device__ int   g_writePos[NEXP];
__device__ int   g_top2[T_TOK * 2];
__device__ int   g_entries[TOTAL];
__device__ float g_h1[(size_t)TOTAL * FFN_DIM];
__device__ float g_partial[2][T_TOK][HID];

__device__ __forceinline__ u64t pack2(float a, float b) {
    u64t r;
    asm("mov.b64 %0, {%1, %2};" : "=l"(r) : "f"(a), "f"(b));
    return r;
}
__device__ __forceinline__ void unpack2(u64t v, float& lo, float& hi) {
    asm("mov.b64 {%0, %1}, %2;" : "=f"(lo), "=f"(hi) : "l"(v));
}
__device__ __forceinline__ void fma2(u64t& c, u64t a, u64t b) {
    asm("fma.rn.f32x2 %0, %1, %2, %0;" : "+l"(c) : "l"(a), "l"(b));
}

// ---------------- routing ----------------
__global__ void zero_counts_kernel() {
    if (threadIdx.x < NEXP) g_counts[threadIdx.x] = 0;
}

__global__ void gate_kernel(const float* __restrict__ x,
                            const float* __restrict__ gate_w,
                            const float* __restrict__ gate_b) {
    int warp = (blockIdx.x * blockDim.x + threadIdx.x) >> 5;
    int lane = threadIdx.x & 31;
    if (warp >= T_TOK) return;
    const float* xr = x + (size_t)warp * HID;
    float acc[NEXP];
#pragma unroll
    for (int e = 0; e < NEXP; e++) acc[e] = 0.f;
    for (int h = lane; h < HID; h += 32) {
        float xv = xr[h];
#pragma unroll
        for (int e = 0; e < NEXP; e++) acc[e] += xv * gate_w[h * NEXP + e];
    }
#pragma unroll
    for (int e = 0; e < NEXP; e++)
#pragma unroll
        for (int o = 16; o > 0; o >>= 1)
            acc[e] += __shfl_down_sync(0xffffffffu, acc[e], o);
    if (lane == 0) {
        float v1 = -3.4e38f, v2 = -3.4e38f;
        int i1 = 0, i2 = 0;
#pragma unroll
        for (int e = 0; e < NEXP; e++) {
            float v = acc[e] + gate_b[e];
            if (v > v1) { v2 = v1; i2 = i1; v1 = v; i1 = e; }
            else if (v > v2) { v2 = v; i2 = e; }
        }
        g_top2[warp * 2 + 0] = i1;
        g_top2[warp * 2 + 1] = i2;
        atomicAdd(&g_counts[i1], 1);
        atomicAdd(&g_counts[i2], 1);
    }
}

__global__ void scan_kernel() {
    if (threadIdx.x == 0) {
        int off = 0;
        for (int e = 0; e < NEXP; e++) {
            g_offsets[e] = off; g_writePos[e] = off; off += g_counts[e];
        }
    }
}

__global__ void fill_kernel() {
    int t = blockIdx.x * blockDim.x + threadIdx.x;
    if (t >= T_TOK) return;
    int p0 = atomicAdd(&g_writePos[g_top2[t * 2 + 0]], 1);
    g_entries[p0] = t * 2;
    int p1 = atomicAdd(&g_writePos[g_top2[t * 2 + 1]], 1);
    g_entries[p1] = t * 2 + 1;
}

// ---------------- GEMM1: h1 = relu(gather(x) @ w1[e] + b1) ----------------
__global__ __launch_bounds__(NTHREADS, 2)
void gemm1_kernel(const float* __restrict__ x,
                  const float* __restrict__ w1,
                  const float* __restrict__ b1) {
    const int e  = blockIdx.z;
    const int mt = blockIdx.y;
    const int nt = blockIdx.x;
    const int count = g_counts[e];
    if (mt * BM >= count) return;
    const int base = g_offsets[e];

    __shared__ __align__(16) float As[BK][BM + 4];
    __shared__ __align__(16) float Bs[BK][BN];

    const int tid = threadIdx.x;
    const int ty = tid >> 4, tx = tid & 15;
    const int aRow0 = tid >> 2;
    const int aCol  = (tid & 3) << 2;
    const int bRow0 = tid >> 5;
    const int bCol  = (tid & 31) << 2;

    const float* Bmat = w1 + (size_t)e * HID * FFN_DIM;

    const float* aPtr[2];
#pragma unroll
    for (int p = 0; p < 2; p++) {
        int gi  = base + mt * BM + aRow0 + p * 64;
        int gci = min(gi, TOTAL - 1);
        int tok = (g_entries[gci] >> 1) & (T_TOK - 1);
        aPtr[p] = x + (size_t)tok * HID + aCol;
    }
    const float* bPtr = Bmat + (size_t)bRow0 * FFN_DIM + nt * BN + bCol;

    u64t c2[8][4];
#pragma unroll
    for (int i = 0; i < 8; i++)
#pragma unroll
        for (int j = 0; j < 4; j++) c2[i][j] = 0ull;

    float4 aReg[2], bReg[2];
    const int KT = HID / BK;
#pragma unroll
    for (int p = 0; p < 2; p++) aReg[p] = *(const float4*)(aPtr[p]);
#pragma unroll
    for (int p = 0; p < 2; p++) bReg[p] = *(const float4*)(bPtr + (size_t)(p * 8) * FFN_DIM);

    for (int kt = 0; kt < KT; kt++) {
#pragma unroll
        for (int p = 0; p < 2; p++) {
            int row = aRow0 + p * 64;
            As[aCol + 0][row] = aReg[p].x;
            As[aCol + 1][row] = aReg[p].y;
            As[aCol + 2][row] = aReg[p].z;
            As[aCol + 3][row] = aReg[p].w;
            *(float4*)&Bs[bRow0 + p * 8][bCol] = bReg[p];
        }
        __syncthreads();
        if (kt + 1 < KT) {
            int koff = (kt + 1) * BK;
#pragma unroll
            for (int p = 0; p < 2; p++) aReg[p] = *(const float4*)(aPtr[p] + koff);
#pragma unroll
            for (int p = 0; p < 2; p++)
                bReg[p] = *(const float4*)(bPtr + (size_t)(koff + p * 8) * FFN_DIM);
        }
#pragma unroll
        for (int k = 0; k < BK; k++) {
            float4 a0 = *(const float4*)&As[k][ty * 8];
            float4 a1 = *(const float4*)&As[k][ty * 8 + 4];
            ulonglong2 bq0 = *(const ulonglong2*)&Bs[k][tx * 8];
            ulonglong2 bq1 = *(const ulonglong2*)&Bs[k][tx * 8 + 4];
            u64t bv[4] = {bq0.x, bq0.y, bq1.x, bq1.y};
            float av[8] = {a0.x, a0.y, a0.z, a0.w, a1.x, a1.y, a1.z, a1.w};
            u64t a2[8];
#pragma unroll
            for (int i = 0; i < 8; i++) a2[i] = pack2(av[i], av[i]);
#pragma unroll
            for (int i = 0; i < 8; i++)
#pragma unroll
                for (int j = 0; j < 4; j++) fma2(c2[i][j], a2[i], bv[j]);
        }
        __syncthreads();
    }

    float bias[8];
    const float* b1p = b1 + (size_t)e * FFN_DIM + nt * BN + tx * 8;
#pragma unroll
    for (int j = 0; j < 8; j++) bias[j] = b1p[j];

#pragma unroll
    for (int i = 0; i < 8; i++) {
        int row = ty * 8 + i;
        if (mt * BM + row < count) {
            int gi = base + mt * BM + row;
            float* dst = g_h1 + (size_t)gi * FFN_DIM + nt * BN + tx * 8;
            float v[8];
#pragma unroll
            for (int j = 0; j < 4; j++) unpack2(c2[i][j], v[2 * j], v[2 * j + 1]);
            float4 o0, o1;
            o0.x = fmaxf(v[0] + bias[0], 0.f);
            o0.y = fmaxf(v[1] + bias[1], 0.f);
            o0.z = fmaxf(v[2] + bias[2], 0.f);
            o0.w = fmaxf(v[3] + bias[3], 0.f);
            o1.x = fmaxf(v[4] + bias[4], 0.f);
            o1.y = fmaxf(v[5] + bias[5], 0.f);
            o1.z = fmaxf(v[6] + bias[6], 0.f);
            o1.w = fmaxf(v[7] + bias[7], 0.f);
            *(float4*)(dst)     = o0;
            *(float4*)(dst + 4) = o1;
        }
    }
}

// ---------------- GEMM2: partial[slot][tok] = h1 @ w2[e] + b2 ----------------
__global__ __launch_bounds__(NTHREADS, 2)
void gemm2_kernel(const float* __restrict__ w2,
                  const float* __restrict__ b2) {
    const int e  = blockIdx.z;
    const int mt = blockIdx.y;
    const int nt = blockIdx.x;
    const int count = g_counts[e];
    if (mt * BM >= count) return;
    const int base = g_offsets[e];

    __shared__ __align__(16) float As[BK][BM + 4];
    __shared__ __align__(16) float Bs[BK][BN];

    const int tid = threadIdx.x;
    const int ty = tid >> 4, tx = tid & 15;
    const int aRow0 = tid >> 2;
    const int aCol  = (tid & 3) << 2;
    const int bRow0 = tid >> 5;
    const int bCol  = (tid & 31) << 2;

    const float* Bmat = w2 + (size_t)e * FFN_DIM * HID;

    const float* aPtr[2];
#pragma unroll
    for (int p = 0; p < 2; p++) {
        int gi  = base + mt * BM + aRow0 + p * 64;
        int gci = min(gi, TOTAL - 1);
        aPtr[p] = g_h1 + (size_t)gci * FFN_DIM + aCol;
    }
    const float* bPtr = Bmat + (size_t)bRow0 * HID + nt * BN + bCol;

    u64t c2[8][4];
#pragma unroll
    for (int i = 0; i < 8; i++)
#pragma unroll
        for (int j = 0; j < 4; j++) c2[i][j] = 0ull;

    float4 aReg[2], bReg[2];
    const int KT = FFN_DIM / BK;
#pragma unroll
    for (int p = 0; p < 2; p++) aReg[p] = *(const float4*)(aPtr[p]);
#pragma unroll
    for (int p = 0; p < 2; p++) bReg[p] = *(const float4*)(bPtr + (size_t)(p * 8) * HID);

    for (int kt = 0; kt < KT; kt++) {
#pragma unroll
        for (int p = 0; p < 2; p++) {
            int row = aRow0 + p * 64;
            As[aCol + 0][row] = aReg[p].x;
            As[aCol + 1][row] = aReg[p].y;
            As[aCol + 2][row] = aReg[p].z;
            As[aCol + 3][row] = aReg[p].w;
            *(float4*)&Bs[bRow0 + p * 8][bCol] = bReg[p];
        }
        __syncthreads();
        if (kt + 1 < KT) {
            int koff = (kt + 1) * BK;
#pragma unroll
            for (int p = 0; p < 2; p++) aReg[p] = *(const float4*)(aPtr[p] + koff);
#pragma unroll
            for (int p = 0; p < 2; p++)
                bReg[p] = *(const float4*)(bPtr + (size_t)(koff + p * 8) * HID);
        }
#pragma unroll
        for (int k = 0; k < BK; k++) {
            float4 a0 = *(const float4*)&As[k][ty * 8];
            float4 a1 = *(const float4*)&As[k][ty * 8 + 4];
            ulonglong2 bq0 = *(const ulonglong2*)&Bs[k][tx * 8];
            ulonglong2 bq1 = *(const ulonglong2*)&Bs[k][tx * 8 + 4];
            u64t bv[4] = {bq0.x, bq0.y, bq1.x, bq1.y};
            float av[8] = {a0.x, a0.y, a0.z, a0.w, a1.x, a1.y, a1.z, a1.w};
            u64t a2[8];
#pragma unroll
            for (int i = 0; i < 8; i++) a2[i] = pack2(av[i], av[i]);
#pragma unroll
            for (int i = 0; i < 8; i++)
#pragma unroll
                for (int j = 0; j < 4; j++) fma2(c2[i][j], a2[i], bv[j]);
        }
        __syncthreads();
    }

    float bias[8];
    const float* b2p = b2 + (size_t)e * HID + nt * BN + tx * 8;
#pragma unroll
    for (int j = 0; j < 8; j++) bias[j] = b2p[j];

#pragma unroll
    for (int i = 0; i < 8; i++) {
        int row = ty * 8 + i;
        if (mt * BM + row < count) {
            int gi = base + mt * BM + row;
            int entry = g_entries[gi];
            int tok  = entry >> 1;
            int slot = entry & 1;
            float* dst = &g_partial[slot][tok][nt * BN + tx * 8];
            float v[8];
#pragma unroll
            for (int j = 0; j < 4; j++) unpack2(c2[i][j], v[2 * j], v[2 * j + 1]);
            float4 o0, o1;
            o0.x = v[0] + bias[0];
            o0.y = v[1] + bias[1];
            o0.z = v[2] + bias[2];
            o0.w = v[3] + bias[3];
            o1.x = v[4] + bias[4];
            o1.y = v[5] + bias[5];
            o1.z = v[6] + bias[6];
            o1.w = v[7] + bias[7];
            *(float4*)(dst)     = o0;
            *(float4*)(dst + 4) = o1;
        }
    }
}

// ---------------- combine ----------------
__global__ void combine_kernel(float* __restrict__ out) {
    int i = blockIdx.x * blockDim.x + threadIdx.x;
    const int n4 = T_TOK * HID / 4;
    if (i < n4) {
        const float4* p0 = (const float4*)&g_partial[0][0][0];
        const float4* p1 = (const float4*)&g_partial[1][0][0];
        float4 a = p0[i], b = p1[i], r;
        r.x = a.x + b.x; r.y = a.y + b.y; r.z = a.z + b.z; r.w = a.w + b.w;
        ((float4*)out)[i] = r;
    }
}

// ---------------- launch ----------------
extern "C" void kernel_launch(void* const* d_in, const int* in_sizes, int n_in,
                              void* d_out, int out_size) {
    const float* x      = (const float*)d_in[0];
    const float* gate_w = (const float*)d_in[1];
    const float* gate_b = (const float*)d_in[2];
    const float* w1     = (const float*)d_in[3];
    const float* b1     = (const float*)d_in[4];
    const float* w2     = (const float*)d_in[5];
    const float* b2     = (const float*)d_in[6];
    float* out = (float*)d_out;

    zero_counts_kernel<<<1, 32>>>();
    gate_kernel<<<T_TOK / 8, 256>>>(x, gate_w, gate_b);
    scan_kernel<<<1, 32>>>();
    fill_kernel<<<T_TOK / 256, 256>>>();

    dim3 g1(FFN_DIM / BN, (T_TOK + BM - 1) / BM, NEXP);
    gemm1_kernel<<<g1, NTHREADS>>>(x, w1, b1);

    dim3 g2(HID / BN, (T_TOK + BM - 1) / BM, NEXP);
    gemm2_kernel<<<g2, NTHREADS>>>(w2, b2);

    combine_kernel<<<(T_TOK * HID / 4 + 255) / 256, 256>>>(out);
}